// round 1
// baseline (speedup 1.0000x reference)
#include <cuda_runtime.h>

#define BATCH 524288

__device__ __forceinline__ float2 cmul(float2 a, float2 b) {
    return make_float2(fmaf(a.x, b.x, -a.y * b.y), fmaf(a.x, b.y, a.y * b.x));
}

__global__ void __launch_bounds__(256) quantum_layer_kernel(
    const float4* __restrict__ x, const float* __restrict__ w,
    float4* __restrict__ out)
{
    // cos/sin of half-angles for the 16 weight gates (shared per block)
    __shared__ float tc[16], ts[16];
    if (threadIdx.x < 16) {
        float a = 0.5f * w[threadIdx.x];
        float s, c;
        sincosf(a, &s, &c);
        tc[threadIdx.x] = c;
        ts[threadIdx.x] = s;
    }
    __syncthreads();

    unsigned b = blockIdx.x * 256u + threadIdx.x;
    if (b >= BATCH) return;
    float4 xv = x[b];
    float xs[4] = {xv.x, xv.y, xv.z, xv.w};

    // ---- Input RY + layer-0 RZ,RY applied per-qubit on 2-vectors (product state) ----
    float2 u0[4], u1[4];
    #pragma unroll
    for (int q = 0; q < 4; q++) {
        float sx, cx;
        __sincosf(0.5f * xs[q], &sx, &cx);
        float cz = tc[2 * q + 0], sz = ts[2 * q + 0];  // weights[0,q,0] (RZ)
        float cy = tc[2 * q + 1], sy = ts[2 * q + 1];  // weights[0,q,1] (RY)
        // after RY(x): v = (cx, sx) real; after RZ: v0 *= e^{-iθ/2}, v1 *= e^{+iθ/2}
        float2 v0 = make_float2(cx * cz, -cx * sz);
        float2 v1 = make_float2(sx * cz,  sx * sz);
        // RY(w1): u0 = cy*v0 - sy*v1 ; u1 = sy*v0 + cy*v1 (real coefficients)
        u0[q] = make_float2(fmaf(cy, v0.x, -sy * v1.x), fmaf(cy, v0.y, -sy * v1.y));
        u1[q] = make_float2(fmaf(sy, v0.x,  cy * v1.x), fmaf(sy, v0.y,  cy * v1.y));
    }

    // ---- Tensor product into 16 amplitudes. index j = b0*8 + b1*4 + b2*2 + b3 ----
    float2 a01[4], a23[4], amp[16];
    a01[0] = cmul(u0[0], u0[1]); a01[1] = cmul(u0[0], u1[1]);
    a01[2] = cmul(u1[0], u0[1]); a01[3] = cmul(u1[0], u1[1]);
    a23[0] = cmul(u0[2], u0[3]); a23[1] = cmul(u0[2], u1[3]);
    a23[2] = cmul(u1[2], u0[3]); a23[3] = cmul(u1[2], u1[3]);
    #pragma unroll
    for (int i = 0; i < 4; i++)
        #pragma unroll
        for (int j = 0; j < 4; j++)
            amp[i * 4 + j] = cmul(a01[i], a23[j]);

    // ---- CNOT ring (0,1)(1,2)(2,3)(3,0) == compile-time permutation ----
    // new[j] = old[perm[j]], perm[(b0,b1,b2,b3)] = (b0^b3, b1^b0^b3, b2^b1, b3^b2)
    const int perm[16] = {0, 13, 3, 14, 6, 11, 5, 8, 12, 1, 15, 2, 10, 7, 9, 4};
    float2 st[16];
    #pragma unroll
    for (int j = 0; j < 16; j++) st[j] = amp[perm[j]];

    // ---- Layer 1: RZ(w[1,q,0]) then RY(w[1,q,1]) per qubit, on full state ----
    #pragma unroll
    for (int q = 0; q < 4; q++) {
        float cz = tc[8 + 2 * q + 0], sz = ts[8 + 2 * q + 0];
        float cy = tc[8 + 2 * q + 1], sy = ts[8 + 2 * q + 1];
        const int mask = 1 << (3 - q);
        // RZ: bit==0 -> *(cz - i sz), bit==1 -> *(cz + i sz)
        #pragma unroll
        for (int i = 0; i < 16; i++) {
            float re = st[i].x, im = st[i].y;
            if (i & mask)
                st[i] = make_float2(fmaf(re, cz, -im * sz), fmaf(im, cz,  re * sz));
            else
                st[i] = make_float2(fmaf(re, cz,  im * sz), fmaf(im, cz, -re * sz));
        }
        // RY: pairs (i, i|mask)
        #pragma unroll
        for (int i = 0; i < 16; i++) {
            if (!(i & mask)) {
                float2 a = st[i], c = st[i | mask];
                st[i]        = make_float2(fmaf(cy, a.x, -sy * c.x), fmaf(cy, a.y, -sy * c.y));
                st[i | mask] = make_float2(fmaf(sy, a.x,  cy * c.x), fmaf(sy, a.y,  cy * c.y));
            }
        }
    }

    // ---- Second CNOT ring folded into the readout: final[j] = st[perm[j]] ----
    // probs p[j] = |st[perm[j]]|^2 ; <Z_q> = sum_j p[j]*(1 - 2*bit_q(j))
    float tot = 0.0f, s0[4] = {0.0f, 0.0f, 0.0f, 0.0f};
    #pragma unroll
    for (int j = 0; j < 16; j++) {
        float2 a = st[perm[j]];
        float p = fmaf(a.x, a.x, a.y * a.y);
        tot += p;
        #pragma unroll
        for (int q = 0; q < 4; q++)
            if (((j >> (3 - q)) & 1) == 0) s0[q] += p;
    }
    float4 o;
    o.x = fmaf(2.0f, s0[0], -tot);
    o.y = fmaf(2.0f, s0[1], -tot);
    o.z = fmaf(2.0f, s0[2], -tot);
    o.w = fmaf(2.0f, s0[3], -tot);
    out[b] = o;
}

extern "C" void kernel_launch(void* const* d_in, const int* in_sizes, int n_in,
                              void* d_out, int out_size) {
    const float4* x = (const float4*)d_in[0];
    const float*  w = (const float*)d_in[1];
    float4* out = (float4*)d_out;
    quantum_layer_kernel<<<BATCH / 256, 256>>>(x, w, out);
}